// round 8
// baseline (speedup 1.0000x reference)
#include <cuda_runtime.h>
#include <cuda_bf16.h>

typedef unsigned long long ull;
typedef unsigned int u32;

#define PIXN 50176
#define KDIM 384

// ---------------- scratch (static device allocations) ----------------
__device__ float g_qkv[57802752];                 // [PIXN][1152] f32 (rolled space)
__device__ __nv_bfloat16 g_xh[19267584];          // rolled x, bf16 hi
__device__ __nv_bfloat16 g_xl[19267584];          // rolled x, bf16 lo
__device__ __nv_bfloat16 g_ah[19267584];          // attention out hi (rolled space)
__device__ __nv_bfloat16 g_al[19267584];          // attention out lo
__device__ __nv_bfloat16 g_wqh[442368];
__device__ __nv_bfloat16 g_wql[442368];
__device__ __nv_bfloat16 g_woh[147456];
__device__ __nv_bfloat16 g_wol[147456];

// ---------------- helpers ----------------
__device__ __forceinline__ int roll3(int m) {
    int b = m / 3136; int p = m - b * 3136;
    int i = p / 56;   int j = p - i * 56;
    i += 3; if (i >= 56) i -= 56;
    j += 3; if (j >= 56) j -= 56;
    return b * 3136 + i * 56 + j;
}

__device__ __forceinline__ ull fpack(float x, float y) {
    ull r; asm("mov.b64 %0, {%1, %2};" : "=l"(r) : "f"(x), "f"(y)); return r;
}
__device__ __forceinline__ void ffma2(ull &c, ull a, ull b) {
    asm("fma.rn.f32x2 %0, %1, %2, %0;" : "+l"(c) : "l"(a), "l"(b));
}
__device__ __forceinline__ float2 funpack(ull v) {
    float2 r; asm("mov.b64 {%0, %1}, %2;" : "=f"(r.x), "=f"(r.y) : "l"(v)); return r;
}
__device__ __forceinline__ u32 s2u(const void* p) {
    u32 a; asm("{ .reg .u64 t; cvta.to.shared.u64 t, %1; cvt.u32.u64 %0, t; }" : "=r"(a) : "l"(p));
    return a;
}
__device__ __forceinline__ void bsplit(float v, __nv_bfloat16& h, __nv_bfloat16& l) {
    h = __float2bfloat16(v);
    l = __float2bfloat16(v - __bfloat162float(h));
}
__device__ __forceinline__ void cp_async16(u32 d, const void* g) {
    asm volatile("cp.async.cg.shared.global [%0], [%1], 16;" :: "r"(d), "l"(g) : "memory");
}
__device__ __forceinline__ void ldsm4(u32* r, u32 addr) {
    asm volatile("ldmatrix.sync.aligned.m8n8.x4.shared.b16 {%0,%1,%2,%3}, [%4];"
                 : "=r"(r[0]), "=r"(r[1]), "=r"(r[2]), "=r"(r[3]) : "r"(addr));
}
__device__ __forceinline__ void mma_bf16(float* c, const u32* a, const u32* b) {
    asm volatile("mma.sync.aligned.m16n8k16.row.col.f32.bf16.bf16.f32 "
                 "{%0,%1,%2,%3},{%4,%5,%6,%7},{%8,%9},{%0,%1,%2,%3};"
                 : "+f"(c[0]), "+f"(c[1]), "+f"(c[2]), "+f"(c[3])
                 : "r"(a[0]), "r"(a[1]), "r"(a[2]), "r"(a[3]), "r"(b[0]), "r"(b[1]));
}

// ---------------- conversion kernels ----------------
__global__ void conv_roll_kernel(const float* __restrict__ x,
                                 __nv_bfloat16* __restrict__ hi,
                                 __nv_bfloat16* __restrict__ lo)
{
    int idx = blockIdx.x * 256 + threadIdx.x;       // over float4, PIXN*96 total
    if (idx >= PIXN * 96) return;
    int m = idx / 96, j = idx - m * 96;
    int src = roll3(m);
    float4 v = ((const float4*)x)[(size_t)src * 96 + j];
    __nv_bfloat16 h0, h1, h2, h3, l0, l1, l2, l3;
    bsplit(v.x, h0, l0); bsplit(v.y, h1, l1); bsplit(v.z, h2, l2); bsplit(v.w, h3, l3);
    __nv_bfloat162* hp = (__nv_bfloat162*)(hi + (size_t)m * 384 + j * 4);
    __nv_bfloat162* lp = (__nv_bfloat162*)(lo + (size_t)m * 384 + j * 4);
    hp[0] = __nv_bfloat162{h0, h1}; hp[1] = __nv_bfloat162{h2, h3};
    lp[0] = __nv_bfloat162{l0, l1}; lp[1] = __nv_bfloat162{l2, l3};
}

__global__ void conv_plain_kernel(const float* __restrict__ a,
                                  __nv_bfloat16* __restrict__ hi,
                                  __nv_bfloat16* __restrict__ lo, int n4)
{
    int idx = blockIdx.x * 256 + threadIdx.x;
    if (idx >= n4) return;
    float4 v = ((const float4*)a)[idx];
    __nv_bfloat16 h0, h1, h2, h3, l0, l1, l2, l3;
    bsplit(v.x, h0, l0); bsplit(v.y, h1, l1); bsplit(v.z, h2, l2); bsplit(v.w, h3, l3);
    __nv_bfloat162* hp = (__nv_bfloat162*)(hi + (size_t)idx * 4);
    __nv_bfloat162* lp = (__nv_bfloat162*)(lo + (size_t)idx * 4);
    hp[0] = __nv_bfloat162{h0, h1}; hp[1] = __nv_bfloat162{h2, h3};
    lp[0] = __nv_bfloat162{l0, l1}; lp[1] = __nv_bfloat162{l2, l3};
}

// ---------------- warp-MMA split-bf16 GEMM (R6 structure, unchanged) ----------------
#define MATB  8192             // 128 rows * 64B per matrix
#define STAGE 32768            // 4 matrices (Ah, Al, Bh, Bl)
#define NSTG  3
#define GEMM_SMEM (NSTG * STAGE)
#define NCHUNK 12

__device__ __forceinline__ u32 sw_addr(u32 base, int row, int kc) {
    return base + row * 64 + ((((u32)kc >> 3) ^ (((u32)row >> 1) & 3)) << 4);
}

template<bool BIAS, bool ROLLOUT>
__global__ __launch_bounds__(256, 2)
void gemm_mma(const __nv_bfloat16* __restrict__ Ah, const __nv_bfloat16* __restrict__ Al,
              const __nv_bfloat16* __restrict__ Bh, const __nv_bfloat16* __restrict__ Bl,
              const float* __restrict__ bias, float* __restrict__ C, int N)
{
    extern __shared__ char smem[];
    const int tid = threadIdx.x;
    const int wid = tid >> 5, lane = tid & 31;
    const int mBase = blockIdx.y * 128, nBase = blockIdx.x * 128;
    const int wm = wid & 3, wn = wid >> 2;

    const u32 s0 = s2u(smem);
    const char* Ahc = (const char*)Ah;
    const char* Alc = (const char*)Al;
    const char* Bhc = (const char*)Bh;
    const char* Blc = (const char*)Bl;

    float c[2][8][4];
#pragma unroll
    for (int i = 0; i < 2; i++)
#pragma unroll
        for (int j = 0; j < 8; j++)
#pragma unroll
            for (int k = 0; k < 4; k++) c[i][j][k] = 0.f;

    const int lmat = lane >> 3;
    const int arow0 = wm * 32 + ((lmat & 1) ? 8 : 0) + (lane & 7);
    const int akc0  = (lmat & 2) ? 8 : 0;
    const int brow0 = wn * 64 + ((lmat & 2) ? 8 : 0) + (lane & 7);
    const int bkc0  = (lmat & 1) ? 8 : 0;

    auto load_chunk = [&](int ck, int st) {
        u32 sbase = s0 + st * STAGE;
#pragma unroll
        for (int v = 0; v < 8; v++) {
            int idx = v * 256 + tid;
            int mat = idx >> 9;
            int r   = (idx >> 2) & 127;
            int cc  = idx & 3;
            const char* gb = (mat < 2) ? ((mat == 0) ? Ahc : Alc)
                                       : ((mat == 2) ? Bhc : Blc);
            int rbase = (mat < 2) ? mBase : nBase;
            const char* g = gb + (size_t)(rbase + r) * 768 + ck * 64 + cc * 16;
            u32 swg = (u32)cc ^ (((u32)r >> 1) & 3);
            cp_async16(sbase + mat * MATB + r * 64 + swg * 16, g);
        }
        asm volatile("cp.async.commit_group;" ::: "memory");
    };

    auto compute = [&](int st) {
        u32 sbase = s0 + st * STAGE;
#pragma unroll
        for (int p = 0; p < 3; p++) {
            u32 Abase = sbase + ((p == 1) ? MATB : 0);
            u32 Bbase = sbase + ((p == 2) ? 3 * MATB : 2 * MATB);
#pragma unroll
            for (int ks = 0; ks < 2; ks++) {
                const int kb = ks * 16;
                u32 a[2][4];
                ldsm4(a[0], sw_addr(Abase, arow0,      kb + akc0));
                ldsm4(a[1], sw_addr(Abase, arow0 + 16, kb + akc0));
#pragma unroll
                for (int nt = 0; nt < 8; nt += 2) {
                    u32 t[4];
                    ldsm4(t, sw_addr(Bbase, brow0 + nt * 8, kb + bkc0));
                    mma_bf16(c[0][nt],     a[0], t);
                    mma_bf16(c[1][nt],     a[1], t);
                    mma_bf16(c[0][nt + 1], a[0], t + 2);
                    mma_bf16(c[1][nt + 1], a[1], t + 2);
                }
            }
        }
    };

    load_chunk(0, 0);
    load_chunk(1, 1);
    int st = 0, pst = 2;
#pragma unroll 1
    for (int ck = 0; ck < NCHUNK; ck++) {
        if (ck < NCHUNK - 1)
            asm volatile("cp.async.wait_group 1;" ::: "memory");
        else
            asm volatile("cp.async.wait_group 0;" ::: "memory");
        __syncthreads();
        if (ck < NCHUNK - 2) load_chunk(ck + 2, pst);
        compute(st);
        st = (st == NSTG - 1) ? 0 : st + 1;
        pst = (pst == NSTG - 1) ? 0 : pst + 1;
    }

#pragma unroll
    for (int mt = 0; mt < 2; mt++) {
#pragma unroll
        for (int half = 0; half < 2; half++) {
            int row = mBase + wm * 32 + mt * 16 + (lane >> 2) + half * 8;
            if (ROLLOUT) row = roll3(row);
            float* cp = C + (size_t)row * N + nBase + wn * 64 + (lane & 3) * 2;
#pragma unroll
            for (int nt = 0; nt < 8; nt++) {
                float2 v;
                v.x = c[mt][nt][half * 2 + 0];
                v.y = c[mt][nt][half * 2 + 1];
                if (BIAS) {
                    int col = nBase + wn * 64 + nt * 8 + (lane & 3) * 2;
                    v.x += bias[col]; v.y += bias[col + 1];
                }
                *(float2*)(cp + nt * 8) = v;
            }
        }
    }
}

// ---------------- windowed attention: head-pipelined ----------------
// One block per (window, batch); loops over 12 heads with a 3-stage cp.async
// pipeline (stage head h+2 while computing head h). 256 threads.
#define SC 52
#define TOKF 36                 // floats per token row in smem (144B)
#define STAGEF (3 * 49 * TOKF)  // q,k,v for one head: 5292 floats
#define SC_OFF (3 * STAGEF)               // 15876
#define REL_OFF (SC_OFF + 49 * SC)        // 18424
#define ATTN_SMEM ((REL_OFF + 2028) * 4)  // 81808 bytes

__global__ __launch_bounds__(256)
void attn_kernel(const float* __restrict__ rel, const float* __restrict__ qkv,
                 __nv_bfloat16* __restrict__ oh, __nv_bfloat16* __restrict__ ol)
{
    extern __shared__ float sm[];
    const int win = blockIdx.x;
    const int b   = blockIdx.y;
    const int tid = threadIdx.x;
    const int warp = tid >> 5, lane = tid & 31;

    const int wi = win >> 3, wj = win & 7;
    const bool masked = (wi == 7);

    float* sc      = sm + SC_OFF;
    float* rel_all = sm + REL_OFF;
    const u32 smb = s2u(sm);

    // rel table for all heads, coalesced
    for (int i = tid; i < 2028; i += 256) rel_all[i] = rel[i];

    const size_t base = (size_t)b * 3136 * 1152;

    // stage loader: q/k/v of head h into stage s (cp.async, one commit group)
    auto prefetch = [&](int h, int s) {
        u32 sb = smb + s * (STAGEF * 4);
        for (int idx = tid; idx < 49 * 8; idx += 256) {
            int tok = idx >> 3, d4 = idx & 7;
            int ti = tok / 7, tj = tok - ti * 7;
            int pix = (wi * 7 + ti) * 56 + (wj * 7 + tj);
            const float* p = qkv + base + (size_t)pix * 1152 + h * 32 + d4 * 4;
            u32 dst = sb + (tok * TOKF + d4 * 4) * 4;
            cp_async16(dst,                     p);
            cp_async16(dst + 49 * TOKF * 4,     p + 384);
            cp_async16(dst + 2 * 49 * TOKF * 4, p + 768);
        }
        asm volatile("cp.async.commit_group;" ::: "memory");
    };

    prefetch(0, 0);
    prefetch(1, 1);

#pragma unroll 1
    for (int h = 0; h < 12; h++) {
        if (h < 11)
            asm volatile("cp.async.wait_group 1;" ::: "memory");
        else
            asm volatile("cp.async.wait_group 0;" ::: "memory");
        __syncthreads();
        if (h < 10) prefetch(h + 2, (h + 2) % 3);

        const int st = h % 3;
        const float* qs = sm + st * STAGEF;
        const float* ks = qs + 49 * TOKF;
        const float* vs = ks + 49 * TOKF;
        const float* rel_h = rel_all;   // indexed as [pos*12 + h]

        // ---- scores: 8 warps = (q-half) x (kk-quarter) ----
        {
            int q = (warp & 1) * 32 + lane;
            int quarter = warp >> 1;
            int kk0 = (quarter == 0) ? 0 : 13 + (quarter - 1) * 12;
            int kk1 = (quarter == 3) ? 49 : kk0 + ((quarter == 0) ? 13 : 12);
            if (q < 49) {
                ull qp[16];
#pragma unroll
                for (int d4 = 0; d4 < 8; d4++) {
                    float4 t = *(const float4*)&qs[q * TOKF + d4 * 4];
                    qp[d4 * 2]     = fpack(t.x, t.y);
                    qp[d4 * 2 + 1] = fpack(t.z, t.w);
                }
                int qi = q / 7, qj = q - qi * 7;
                int ki = kk0 / 7, kj = kk0 - ki * 7;
                const float scale = 0.1767766952966369f;
                for (int kk = kk0; kk < kk1; kk++) {
                    ull a0 = 0, a1 = 0, a2 = 0, a3 = 0;
#pragma unroll
                    for (int d4 = 0; d4 < 8; d4 += 2) {
                        float4 t0 = *(const float4*)&ks[kk * TOKF + d4 * 4];
                        float4 t1 = *(const float4*)&ks[kk * TOKF + d4 * 4 + 4];
                        ffma2(a0, qp[d4 * 2],     fpack(t0.x, t0.y));
                        ffma2(a1, qp[d4 * 2 + 1], fpack(t0.z, t0.w));
                        ffma2(a2, qp[d4 * 2 + 2], fpack(t1.x, t1.y));
                        ffma2(a3, qp[d4 * 2 + 3], fpack(t1.z, t1.w));
                    }
                    float2 h0 = funpack(a0), h1 = funpack(a1);
                    float2 h2 = funpack(a2), h3 = funpack(a3);
                    float dot = (h0.x + h0.y) + (h1.x + h1.y) + (h2.x + h2.y) + (h3.x + h3.y);
                    int pos = ((ki - qi + 6) * 13 + (kj - qj + 6));
                    float s = dot * scale + rel_h[pos * 12 + h];
                    if (masked && ((q >= 28) != (kk >= 28))) s = -1e30f;
                    sc[q * SC + kk] = s;
                    kj++; if (kj == 7) { kj = 0; ki++; }
                }
            }
        }
        __syncthreads();

        // ---- softmax: rows striped over 8 warps ----
        for (int r = warp; r < 49; r += 8) {
            float v0 = sc[r * SC + lane];
            float v1 = (lane + 32 < 49) ? sc[r * SC + lane + 32] : -1e30f;
            float m = fmaxf(v0, v1);
#pragma unroll
            for (int off = 16; off > 0; off >>= 1)
                m = fmaxf(m, __shfl_xor_sync(0xffffffffu, m, off));
            float e0 = __expf(v0 - m);
            float e1 = (lane + 32 < 49) ? __expf(v1 - m) : 0.f;
            float s = e0 + e1;
#pragma unroll
            for (int off = 16; off > 0; off >>= 1)
                s += __shfl_xor_sync(0xffffffffu, s, off);
            float inv = 1.f / s;
            sc[r * SC + lane] = e0 * inv;
            if (lane + 32 < 49) sc[r * SC + lane + 32] = e1 * inv;
        }
        __syncthreads();

        // ---- P @ V : lane = d; warp handles q = warp + 8t ----
        const int d = lane;
        ull acc[7];
#pragma unroll
        for (int t = 0; t < 7; t++) acc[t] = 0ull;

#pragma unroll 1
        for (int it = 0; it < 12; it++) {
            int kk = it * 4;
            float v0 = vs[(kk + 0) * TOKF + d];
            float v1 = vs[(kk + 1) * TOKF + d];
            float v2 = vs[(kk + 2) * TOKF + d];
            float v3 = vs[(kk + 3) * TOKF + d];
            ull v01 = fpack(v0, v1), v23 = fpack(v2, v3);
#pragma unroll
            for (int t = 0; t < 7; t++) {
                int q = warp + 8 * t;
                if (q < 49) {
                    float4 s4 = *(const float4*)&sc[q * SC + kk];
                    ffma2(acc[t], fpack(s4.x, s4.y), v01);
                    ffma2(acc[t], fpack(s4.z, s4.w), v23);
                }
            }
        }
        float v48 = vs[48 * TOKF + d];

#pragma unroll
        for (int t = 0; t < 7; t++) {
            int q = warp + 8 * t;
            if (q < 49) {
                float2 hv = funpack(acc[t]);
                float o = hv.x + hv.y + sc[q * SC + 48] * v48;
                int ti = q / 7, tj = q - ti * 7;
                int pix = (wi * 7 + ti) * 56 + (wj * 7 + tj);
                size_t oidx = ((size_t)b * 3136 + pix) * 384 + h * 32 + d;
                __nv_bfloat16 hh, ll;
                bsplit(o, hh, ll);
                oh[oidx] = hh;
                ol[oidx] = ll;
            }
        }
        __syncthreads();   // PV reads of sc done before next head's score writes
    }
}

// ---------------- launch ----------------
extern "C" void kernel_launch(void* const* d_in, const int* in_sizes, int n_in,
                              void* d_out, int out_size)
{
    const float *x = nullptr, *wqkv = nullptr, *wout = nullptr,
                *bout = nullptr, *rel = nullptr;
    for (int i = 0; i < n_in; i++) {
        switch (in_sizes[i]) {
            case 19267584: x    = (const float*)d_in[i]; break;
            case 442368:   wqkv = (const float*)d_in[i]; break;
            case 147456:   wout = (const float*)d_in[i]; break;
            case 384:      bout = (const float*)d_in[i]; break;
            case 2028:     rel  = (const float*)d_in[i]; break;
        }
    }
    float* out = (float*)d_out;

    void *qkv_p, *xh_p, *xl_p, *ah_p, *al_p, *wqh_p, *wql_p, *woh_p, *wol_p;
    cudaGetSymbolAddress(&qkv_p, g_qkv);
    cudaGetSymbolAddress(&xh_p, g_xh);   cudaGetSymbolAddress(&xl_p, g_xl);
    cudaGetSymbolAddress(&ah_p, g_ah);   cudaGetSymbolAddress(&al_p, g_al);
    cudaGetSymbolAddress(&wqh_p, g_wqh); cudaGetSymbolAddress(&wql_p, g_wql);
    cudaGetSymbolAddress(&woh_p, g_woh); cudaGetSymbolAddress(&wol_p, g_wol);

    cudaFuncSetAttribute(gemm_mma<false, false>,
                         cudaFuncAttributeMaxDynamicSharedMemorySize, GEMM_SMEM);
    cudaFuncSetAttribute(gemm_mma<true, true>,
                         cudaFuncAttributeMaxDynamicSharedMemorySize, GEMM_SMEM);
    cudaFuncSetAttribute(attn_kernel,
                         cudaFuncAttributeMaxDynamicSharedMemorySize, ATTN_SMEM);

    // 0) conversions to split-bf16
    conv_roll_kernel<<<(PIXN * 96 + 255) / 256, 256>>>(
        x, (__nv_bfloat16*)xh_p, (__nv_bfloat16*)xl_p);
    conv_plain_kernel<<<(110592 + 255) / 256, 256>>>(
        wqkv, (__nv_bfloat16*)wqh_p, (__nv_bfloat16*)wql_p, 110592);
    conv_plain_kernel<<<(36864 + 255) / 256, 256>>>(
        wout, (__nv_bfloat16*)woh_p, (__nv_bfloat16*)wol_p, 36864);

    // 1) qkv = roll(x) @ w_qkv^T   (warp MMA)
    {
        dim3 grid(1152 / 128, PIXN / 128);
        gemm_mma<false, false><<<grid, 256, GEMM_SMEM>>>(
            (const __nv_bfloat16*)xh_p, (const __nv_bfloat16*)xl_p,
            (const __nv_bfloat16*)wqh_p, (const __nv_bfloat16*)wql_p,
            nullptr, (float*)qkv_p, 1152);
    }
    // 2) windowed attention (head-pipelined) -> bf16 hi/lo
    {
        dim3 grid(64, 16);
        attn_kernel<<<grid, 256, ATTN_SMEM>>>(rel, (const float*)qkv_p,
                                              (__nv_bfloat16*)ah_p, (__nv_bfloat16*)al_p);
    }
    // 3) out = unroll( att @ w_out^T + b_out )   (warp MMA)
    {
        dim3 grid(384 / 128, PIXN / 128);
        gemm_mma<true, true><<<grid, 256, GEMM_SMEM>>>(
            (const __nv_bfloat16*)ah_p, (const __nv_bfloat16*)al_p,
            (const __nv_bfloat16*)woh_p, (const __nv_bfloat16*)wol_p,
            bout, out, 384);
    }
}

// round 9
// speedup vs baseline: 1.1890x; 1.1890x over previous
#include <cuda_runtime.h>
#include <cuda_bf16.h>

typedef unsigned long long ull;
typedef unsigned int u32;

#define PIXN 50176
#define KDIM 384

// ---------------- scratch (static device allocations) ----------------
__device__ float g_qkv[57802752];                 // [PIXN][1152] f32 (rolled space)
__device__ __nv_bfloat16 g_xh[19267584];          // rolled x, bf16 hi
__device__ __nv_bfloat16 g_xl[19267584];          // rolled x, bf16 lo
__device__ __nv_bfloat16 g_ah[19267584];          // attention out hi (rolled space)
__device__ __nv_bfloat16 g_al[19267584];          // attention out lo
__device__ __nv_bfloat16 g_wqh[442368];
__device__ __nv_bfloat16 g_wql[442368];
__device__ __nv_bfloat16 g_woh[147456];
__device__ __nv_bfloat16 g_wol[147456];

// ---------------- helpers ----------------
__device__ __forceinline__ int roll3(int m) {
    int b = m / 3136; int p = m - b * 3136;
    int i = p / 56;   int j = p - i * 56;
    i += 3; if (i >= 56) i -= 56;
    j += 3; if (j >= 56) j -= 56;
    return b * 3136 + i * 56 + j;
}

__device__ __forceinline__ ull fpack(float x, float y) {
    ull r; asm("mov.b64 %0, {%1, %2};" : "=l"(r) : "f"(x), "f"(y)); return r;
}
__device__ __forceinline__ void ffma2(ull &c, ull a, ull b) {
    asm("fma.rn.f32x2 %0, %1, %2, %0;" : "+l"(c) : "l"(a), "l"(b));
}
__device__ __forceinline__ float2 funpack(ull v) {
    float2 r; asm("mov.b64 {%0, %1}, %2;" : "=f"(r.x), "=f"(r.y) : "l"(v)); return r;
}
__device__ __forceinline__ u32 s2u(const void* p) {
    u32 a; asm("{ .reg .u64 t; cvta.to.shared.u64 t, %1; cvt.u32.u64 %0, t; }" : "=r"(a) : "l"(p));
    return a;
}
__device__ __forceinline__ void bsplit(float v, __nv_bfloat16& h, __nv_bfloat16& l) {
    h = __float2bfloat16(v);
    l = __float2bfloat16(v - __bfloat162float(h));
}
__device__ __forceinline__ void cp_async16(u32 d, const void* g) {
    asm volatile("cp.async.cg.shared.global [%0], [%1], 16;" :: "r"(d), "l"(g) : "memory");
}
__device__ __forceinline__ void ldsm4(u32* r, u32 addr) {
    asm volatile("ldmatrix.sync.aligned.m8n8.x4.shared.b16 {%0,%1,%2,%3}, [%4];"
                 : "=r"(r[0]), "=r"(r[1]), "=r"(r[2]), "=r"(r[3]) : "r"(addr));
}
__device__ __forceinline__ void mma_bf16(float* c, const u32* a, const u32* b) {
    asm volatile("mma.sync.aligned.m16n8k16.row.col.f32.bf16.bf16.f32 "
                 "{%0,%1,%2,%3},{%4,%5,%6,%7},{%8,%9},{%0,%1,%2,%3};"
                 : "+f"(c[0]), "+f"(c[1]), "+f"(c[2]), "+f"(c[3])
                 : "r"(a[0]), "r"(a[1]), "r"(a[2]), "r"(a[3]), "r"(b[0]), "r"(b[1]));
}

// ---------------- conversion kernels ----------------
__global__ void conv_roll_kernel(const float* __restrict__ x,
                                 __nv_bfloat16* __restrict__ hi,
                                 __nv_bfloat16* __restrict__ lo)
{
    int idx = blockIdx.x * 256 + threadIdx.x;       // over float4, PIXN*96 total
    if (idx >= PIXN * 96) return;
    int m = idx / 96, j = idx - m * 96;
    int src = roll3(m);
    float4 v = ((const float4*)x)[(size_t)src * 96 + j];
    __nv_bfloat16 h0, h1, h2, h3, l0, l1, l2, l3;
    bsplit(v.x, h0, l0); bsplit(v.y, h1, l1); bsplit(v.z, h2, l2); bsplit(v.w, h3, l3);
    __nv_bfloat162* hp = (__nv_bfloat162*)(hi + (size_t)m * 384 + j * 4);
    __nv_bfloat162* lp = (__nv_bfloat162*)(lo + (size_t)m * 384 + j * 4);
    hp[0] = __nv_bfloat162{h0, h1}; hp[1] = __nv_bfloat162{h2, h3};
    lp[0] = __nv_bfloat162{l0, l1}; lp[1] = __nv_bfloat162{l2, l3};
}

__global__ void conv_plain_kernel(const float* __restrict__ a,
                                  __nv_bfloat16* __restrict__ hi,
                                  __nv_bfloat16* __restrict__ lo, int n4)
{
    int idx = blockIdx.x * 256 + threadIdx.x;
    if (idx >= n4) return;
    float4 v = ((const float4*)a)[idx];
    __nv_bfloat16 h0, h1, h2, h3, l0, l1, l2, l3;
    bsplit(v.x, h0, l0); bsplit(v.y, h1, l1); bsplit(v.z, h2, l2); bsplit(v.w, h3, l3);
    __nv_bfloat162* hp = (__nv_bfloat162*)(hi + (size_t)idx * 4);
    __nv_bfloat162* lp = (__nv_bfloat162*)(lo + (size_t)idx * 4);
    hp[0] = __nv_bfloat162{h0, h1}; hp[1] = __nv_bfloat162{h2, h3};
    lp[0] = __nv_bfloat162{l0, l1}; lp[1] = __nv_bfloat162{l2, l3};
}

// ---------------- warp-MMA split-bf16 GEMM ----------------
// C(M,N) = A(M,384) @ B(N,384)^T via Ah*Bh + Al*Bh + Ah*Bl, fp32 accumulation.
// Block tile 128x128, 8 warps (32x64 warp tiles), K-chunk 32.
// 3-stage cp.async pipeline, ONE __syncthreads per chunk (prefetch distance 2).
// smem rows: 64B with XOR swizzle; K-step loads each fragment ONCE
// (12 ldsm instead of 18: Ah/Al hoisted, Bh held, Bl streamed).
#define MATB  8192             // 128 rows * 64B per matrix
#define STAGE 32768            // 4 matrices (Ah, Al, Bh, Bl)
#define NSTG  3
#define GEMM_SMEM (NSTG * STAGE)
#define NCHUNK 12

__device__ __forceinline__ u32 sw_addr(u32 base, int row, int kc) {
    return base + row * 64 + ((((u32)kc >> 3) ^ (((u32)row >> 1) & 3)) << 4);
}

template<bool BIAS, bool ROLLOUT>
__global__ __launch_bounds__(256, 2)
void gemm_mma(const __nv_bfloat16* __restrict__ Ah, const __nv_bfloat16* __restrict__ Al,
              const __nv_bfloat16* __restrict__ Bh, const __nv_bfloat16* __restrict__ Bl,
              const float* __restrict__ bias, float* __restrict__ C, int N)
{
    extern __shared__ char smem[];
    const int tid = threadIdx.x;
    const int wid = tid >> 5, lane = tid & 31;
    const int mBase = blockIdx.y * 128, nBase = blockIdx.x * 128;
    const int wm = wid & 3, wn = wid >> 2;

    const u32 s0 = s2u(smem);
    const char* Ahc = (const char*)Ah;
    const char* Alc = (const char*)Al;
    const char* Bhc = (const char*)Bh;
    const char* Blc = (const char*)Bl;

    float c[2][8][4];
#pragma unroll
    for (int i = 0; i < 2; i++)
#pragma unroll
        for (int j = 0; j < 8; j++)
#pragma unroll
            for (int k = 0; k < 4; k++) c[i][j][k] = 0.f;

    const int lmat = lane >> 3;
    const int arow0 = wm * 32 + ((lmat & 1) ? 8 : 0) + (lane & 7);
    const int akc0  = (lmat & 2) ? 8 : 0;
    const int brow0 = wn * 64 + ((lmat & 2) ? 8 : 0) + (lane & 7);
    const int bkc0  = (lmat & 1) ? 8 : 0;

    auto load_chunk = [&](int ck, int st) {
        u32 sbase = s0 + st * STAGE;
#pragma unroll
        for (int v = 0; v < 8; v++) {
            int idx = v * 256 + tid;
            int mat = idx >> 9;
            int r   = (idx >> 2) & 127;
            int cc  = idx & 3;
            const char* gb = (mat < 2) ? ((mat == 0) ? Ahc : Alc)
                                       : ((mat == 2) ? Bhc : Blc);
            int rbase = (mat < 2) ? mBase : nBase;
            const char* g = gb + (size_t)(rbase + r) * 768 + ck * 64 + cc * 16;
            u32 swg = (u32)cc ^ (((u32)r >> 1) & 3);
            cp_async16(sbase + mat * MATB + r * 64 + swg * 16, g);
        }
        asm volatile("cp.async.commit_group;" ::: "memory");
    };

    auto compute = [&](int st) {
        u32 sbase = s0 + st * STAGE;
#pragma unroll
        for (int ks = 0; ks < 2; ks++) {
            const int kb = ks * 16;
            // unique fragments, loaded once
            u32 ah[2][4], al[2][4], bh[4][4];
            ldsm4(ah[0], sw_addr(sbase,            arow0,      kb + akc0));
            ldsm4(ah[1], sw_addr(sbase,            arow0 + 16, kb + akc0));
            ldsm4(al[0], sw_addr(sbase + MATB,     arow0,      kb + akc0));
            ldsm4(al[1], sw_addr(sbase + MATB,     arow0 + 16, kb + akc0));
#pragma unroll
            for (int p = 0; p < 4; p++)
                ldsm4(bh[p], sw_addr(sbase + 2 * MATB, brow0 + p * 16, kb + bkc0));
            // pass 0: Ah * Bh
#pragma unroll
            for (int p = 0; p < 4; p++) {
                mma_bf16(c[0][2 * p],     ah[0], bh[p]);
                mma_bf16(c[1][2 * p],     ah[1], bh[p]);
                mma_bf16(c[0][2 * p + 1], ah[0], bh[p] + 2);
                mma_bf16(c[1][2 * p + 1], ah[1], bh[p] + 2);
            }
            // pass 1: Al * Bh
#pragma unroll
            for (int p = 0; p < 4; p++) {
                mma_bf16(c[0][2 * p],     al[0], bh[p]);
                mma_bf16(c[1][2 * p],     al[1], bh[p]);
                mma_bf16(c[0][2 * p + 1], al[0], bh[p] + 2);
                mma_bf16(c[1][2 * p + 1], al[1], bh[p] + 2);
            }
            // pass 2: Ah * Bl (stream Bl)
#pragma unroll
            for (int p = 0; p < 4; p++) {
                u32 u[4];
                ldsm4(u, sw_addr(sbase + 3 * MATB, brow0 + p * 16, kb + bkc0));
                mma_bf16(c[0][2 * p],     ah[0], u);
                mma_bf16(c[1][2 * p],     ah[1], u);
                mma_bf16(c[0][2 * p + 1], ah[0], u + 2);
                mma_bf16(c[1][2 * p + 1], ah[1], u + 2);
            }
        }
    };

    load_chunk(0, 0);
    load_chunk(1, 1);
    int st = 0, pst = 2;
#pragma unroll 1
    for (int ck = 0; ck < NCHUNK; ck++) {
        if (ck < NCHUNK - 1)
            asm volatile("cp.async.wait_group 1;" ::: "memory");
        else
            asm volatile("cp.async.wait_group 0;" ::: "memory");
        __syncthreads();
        if (ck < NCHUNK - 2) load_chunk(ck + 2, pst);
        compute(st);
        st = (st == NSTG - 1) ? 0 : st + 1;
        pst = (pst == NSTG - 1) ? 0 : pst + 1;
    }

#pragma unroll
    for (int mt = 0; mt < 2; mt++) {
#pragma unroll
        for (int half = 0; half < 2; half++) {
            int row = mBase + wm * 32 + mt * 16 + (lane >> 2) + half * 8;
            if (ROLLOUT) row = roll3(row);
            float* cp = C + (size_t)row * N + nBase + wn * 64 + (lane & 3) * 2;
#pragma unroll
            for (int nt = 0; nt < 8; nt++) {
                float2 v;
                v.x = c[mt][nt][half * 2 + 0];
                v.y = c[mt][nt][half * 2 + 1];
                if (BIAS) {
                    int col = nBase + wn * 64 + nt * 8 + (lane & 3) * 2;
                    v.x += bias[col]; v.y += bias[col + 1];
                }
                *(float2*)(cp + nt * 8) = v;
            }
        }
    }
}

// ---------------- windowed attention (R6 version, proven fastest) ----------------
#define SC 52

__global__ __launch_bounds__(128)
void attn_kernel(const float* __restrict__ rel, const float* __restrict__ qkv,
                 __nv_bfloat16* __restrict__ oh, __nv_bfloat16* __restrict__ ol)
{
    const int h   = blockIdx.x;
    const int win = blockIdx.y;
    const int b   = blockIdx.z;
    const int tid = threadIdx.x;
    const int warp = tid >> 5, lane = tid & 31;

    __shared__ float qs[49 * 36];
    __shared__ float ks[49 * 36];
    __shared__ float vs[49 * 36];
    __shared__ float sc[49 * SC];
    __shared__ float rel_s[169];

    const int wi = win >> 3, wj = win & 7;
    const bool masked = (wi == 7);

    for (int i = tid; i < 169; i += 128) rel_s[i] = rel[i * 12 + h];

    // vectorized gather: 49 tokens x 8 float4-groups per matrix
    const size_t base = (size_t)b * 3136 * 1152 + h * 32;
    for (int idx = tid; idx < 49 * 8; idx += 128) {
        int tok = idx >> 3, d4 = idx & 7;
        int ti = tok / 7, tj = tok - ti * 7;
        int pix = (wi * 7 + ti) * 56 + (wj * 7 + tj);
        const float* p = qkv + base + (size_t)pix * 1152 + d4 * 4;
        *(float4*)&qs[tok * 36 + d4 * 4] = *(const float4*)(p);
        *(float4*)&ks[tok * 36 + d4 * 4] = *(const float4*)(p + 384);
        *(float4*)&vs[tok * 36 + d4 * 4] = *(const float4*)(p + 768);
    }
    __syncthreads();

    // scores: lanes = q; warps split (q-half, kk-half)
    {
        int q = (warp & 1) * 32 + lane;
        int kk0 = (warp >> 1) ? 25 : 0;
        int kk1 = (warp >> 1) ? 49 : 25;
        if (q < 49) {
            ull qp[16];
#pragma unroll
            for (int d4 = 0; d4 < 8; d4++) {
                float4 t = *(const float4*)&qs[q * 36 + d4 * 4];
                qp[d4 * 2]     = fpack(t.x, t.y);
                qp[d4 * 2 + 1] = fpack(t.z, t.w);
            }
            int qi = q / 7, qj = q - qi * 7;
            int ki = kk0 / 7, kj = kk0 - ki * 7;
            const float scale = 0.1767766952966369f;
            for (int kk = kk0; kk < kk1; kk++) {
                ull a0 = 0, a1 = 0, a2 = 0, a3 = 0;
#pragma unroll
                for (int d4 = 0; d4 < 8; d4 += 2) {
                    float4 t0 = *(const float4*)&ks[kk * 36 + d4 * 4];
                    float4 t1 = *(const float4*)&ks[kk * 36 + d4 * 4 + 4];
                    ffma2(a0, qp[d4 * 2],     fpack(t0.x, t0.y));
                    ffma2(a1, qp[d4 * 2 + 1], fpack(t0.z, t0.w));
                    ffma2(a2, qp[d4 * 2 + 2], fpack(t1.x, t1.y));
                    ffma2(a3, qp[d4 * 2 + 3], fpack(t1.z, t1.w));
                }
                float2 h0 = funpack(a0), h1 = funpack(a1);
                float2 h2 = funpack(a2), h3 = funpack(a3);
                float dot = (h0.x + h0.y) + (h1.x + h1.y) + (h2.x + h2.y) + (h3.x + h3.y);
                float s = dot * scale + rel_s[(ki - qi + 6) * 13 + (kj - qj + 6)];
                if (masked && ((q >= 28) != (kk >= 28))) s = -1e30f;
                sc[q * SC + kk] = s;
                kj++; if (kj == 7) { kj = 0; ki++; }
            }
        }
    }
    __syncthreads();

    // softmax per row
    for (int r = warp; r < 49; r += 4) {
        float v0 = sc[r * SC + lane];
        float v1 = (lane + 32 < 49) ? sc[r * SC + lane + 32] : -1e30f;
        float m = fmaxf(v0, v1);
#pragma unroll
        for (int off = 16; off > 0; off >>= 1)
            m = fmaxf(m, __shfl_xor_sync(0xffffffffu, m, off));
        float e0 = __expf(v0 - m);
        float e1 = (lane + 32 < 49) ? __expf(v1 - m) : 0.f;
        float s = e0 + e1;
#pragma unroll
        for (int off = 16; off > 0; off >>= 1)
            s += __shfl_xor_sync(0xffffffffu, s, off);
        float inv = 1.f / s;
        sc[r * SC + lane] = e0 * inv;
        if (lane + 32 < 49) sc[r * SC + lane + 32] = e1 * inv;
    }
    __syncthreads();

    // P @ V : lane = d; warp handles q = warp + 4t (guarded full unroll)
    const int d = lane;
    ull acc[13];
#pragma unroll
    for (int t = 0; t < 13; t++) acc[t] = 0ull;

#pragma unroll 1
    for (int it = 0; it < 12; it++) {
        int kk = it * 4;
        float v0 = vs[(kk + 0) * 36 + d];
        float v1 = vs[(kk + 1) * 36 + d];
        float v2 = vs[(kk + 2) * 36 + d];
        float v3 = vs[(kk + 3) * 36 + d];
        ull v01 = fpack(v0, v1), v23 = fpack(v2, v3);
#pragma unroll
        for (int t = 0; t < 13; t++) {
            int q = warp + 4 * t;
            if (q < 49) {
                float4 s4 = *(const float4*)&sc[q * SC + kk];
                ffma2(acc[t], fpack(s4.x, s4.y), v01);
                ffma2(acc[t], fpack(s4.z, s4.w), v23);
            }
        }
    }
    float v48 = vs[48 * 36 + d];

#pragma unroll
    for (int t = 0; t < 13; t++) {
        int q = warp + 4 * t;
        if (q < 49) {
            float2 hv = funpack(acc[t]);
            float o = hv.x + hv.y + sc[q * SC + 48] * v48;
            int ti = q / 7, tj = q - ti * 7;
            int pix = (wi * 7 + ti) * 56 + (wj * 7 + tj);
            size_t oidx = ((size_t)b * 3136 + pix) * 384 + h * 32 + d;
            __nv_bfloat16 hh, ll;
            bsplit(o, hh, ll);
            oh[oidx] = hh;
            ol[oidx] = ll;
        }
    }
}

// ---------------- launch ----------------
extern "C" void kernel_launch(void* const* d_in, const int* in_sizes, int n_in,
                              void* d_out, int out_size)
{
    const float *x = nullptr, *wqkv = nullptr, *wout = nullptr,
                *bout = nullptr, *rel = nullptr;
    for (int i = 0; i < n_in; i++) {
        switch (in_sizes[i]) {
            case 19267584: x    = (const float*)d_in[i]; break;
            case 442368:   wqkv = (const float*)d_in[i]; break;
            case 147456:   wout = (const float*)d_in[i]; break;
            case 384:      bout = (const float*)d_in[i]; break;
            case 2028:     rel  = (const float*)d_in[i]; break;
        }
    }
    float* out = (float*)d_out;

    void *qkv_p, *xh_p, *xl_p, *ah_p, *al_p, *wqh_p, *wql_p, *woh_p, *wol_p;
    cudaGetSymbolAddress(&qkv_p, g_qkv);
    cudaGetSymbolAddress(&xh_p, g_xh);   cudaGetSymbolAddress(&xl_p, g_xl);
    cudaGetSymbolAddress(&ah_p, g_ah);   cudaGetSymbolAddress(&al_p, g_al);
    cudaGetSymbolAddress(&wqh_p, g_wqh); cudaGetSymbolAddress(&wql_p, g_wql);
    cudaGetSymbolAddress(&woh_p, g_woh); cudaGetSymbolAddress(&wol_p, g_wol);

    cudaFuncSetAttribute(gemm_mma<false, false>,
                         cudaFuncAttributeMaxDynamicSharedMemorySize, GEMM_SMEM);
    cudaFuncSetAttribute(gemm_mma<true, true>,
                         cudaFuncAttributeMaxDynamicSharedMemorySize, GEMM_SMEM);

    // 0) conversions to split-bf16
    conv_roll_kernel<<<(PIXN * 96 + 255) / 256, 256>>>(
        x, (__nv_bfloat16*)xh_p, (__nv_bfloat16*)xl_p);
    conv_plain_kernel<<<(110592 + 255) / 256, 256>>>(
        wqkv, (__nv_bfloat16*)wqh_p, (__nv_bfloat16*)wql_p, 110592);
    conv_plain_kernel<<<(36864 + 255) / 256, 256>>>(
        wout, (__nv_bfloat16*)woh_p, (__nv_bfloat16*)wol_p, 36864);

    // 1) qkv = roll(x) @ w_qkv^T   (warp MMA)
    {
        dim3 grid(1152 / 128, PIXN / 128);
        gemm_mma<false, false><<<grid, 256, GEMM_SMEM>>>(
            (const __nv_bfloat16*)xh_p, (const __nv_bfloat16*)xl_p,
            (const __nv_bfloat16*)wqh_p, (const __nv_bfloat16*)wql_p,
            nullptr, (float*)qkv_p, 1152);
    }
    // 2) windowed attention -> bf16 hi/lo
    {
        dim3 grid(12, 64, 16);
        attn_kernel<<<grid, 128>>>(rel, (const float*)qkv_p,
                                   (__nv_bfloat16*)ah_p, (__nv_bfloat16*)al_p);
    }
    // 3) out = unroll( att @ w_out^T + b_out )   (warp MMA)
    {
        dim3 grid(384 / 128, PIXN / 128);
        gemm_mma<true, true><<<grid, 256, GEMM_SMEM>>>(
            (const __nv_bfloat16*)ah_p, (const __nv_bfloat16*)al_p,
            (const __nv_bfloat16*)woh_p, (const __nv_bfloat16*)wol_p,
            bout, out, 384);
    }
}